// round 3
// baseline (speedup 1.0000x reference)
#include <cuda_runtime.h>

// Problem constants (T=512, B=32, A=64, N=128, H=8)
#define TPB   256
#define ADIM  64
#define NDIM  128
#define HDIM  8

__global__ __launch_bounds__(TPB, 4)
void attn_fused_kernel(const float* __restrict__ agent,
                       const float* __restrict__ Wq, const float* __restrict__ bq,
                       const float* __restrict__ Wk, const float* __restrict__ bk,
                       float* __restrict__ out)
{
    __shared__ float sWq[HDIM][NDIM];   // transposed: sWq[h][n]
    __shared__ float sWk[HDIM][NDIM];
    __shared__ float sbq[HDIM];
    __shared__ float sbk[HDIM];
    __shared__ float qsm[ADIM * HDIM];  // q[a][h] at a*8+h
    __shared__ float ksm[ADIM * HDIM];  // k flat (row-major a*8+h); att reads ksm[h*64+a]

    const int tid = threadIdx.x;
    const long long tb = blockIdx.x;    // (t,b) pair index

    // ---- load weights (transposed) + biases into smem ----
    for (int i = tid; i < NDIM * HDIM; i += TPB) {
        int n = i >> 3, h = i & 7;
        sWq[h][n] = Wq[i];
        sWk[h][n] = Wk[i];
    }
    if (tid < HDIM) { sbq[tid] = bq[tid]; sbk[tid] = bk[tid]; }
    __syncthreads();

    const int r = tid >> 2;   // agent row 0..63
    const int c = tid & 3;    // chunk within row

    // ---- phase 1: fused Q/K projection ----
    // thread reads float4s at indices c + 4k (k=0..7) of its row  -> coalesced LDG.128
    const float4* srow =
        reinterpret_cast<const float4*>(agent + tb * (ADIM * NDIM) + (long long)r * NDIM);

    float accq[HDIM], acck[HDIM];
    #pragma unroll
    for (int h = 0; h < HDIM; h++) { accq[h] = 0.f; acck[h] = 0.f; }

    #pragma unroll
    for (int k = 0; k < 8; k++) {
        float4 s = srow[c + 4 * k];
        const int nb = (c + 4 * k) * 4;
        #pragma unroll
        for (int h = 0; h < HDIM; h++) {
            float4 wq = *reinterpret_cast<const float4*>(&sWq[h][nb]);
            accq[h] += s.x * wq.x + s.y * wq.y + s.z * wq.z + s.w * wq.w;
            float4 wk = *reinterpret_cast<const float4*>(&sWk[h][nb]);
            acck[h] += s.x * wk.x + s.y * wk.y + s.z * wk.z + s.w * wk.w;
        }
    }

    // reduce partial dots across the 4 lanes of this row (lanes r*4 + c, same warp)
    #pragma unroll
    for (int h = 0; h < HDIM; h++) {
        accq[h] += __shfl_xor_sync(0xffffffffu, accq[h], 1);
        accq[h] += __shfl_xor_sync(0xffffffffu, accq[h], 2);
        acck[h] += __shfl_xor_sync(0xffffffffu, acck[h], 1);
        acck[h] += __shfl_xor_sync(0xffffffffu, acck[h], 2);
    }
    // every lane has the full sums; lane c writes h = 2c, 2c+1
    {
        const int h0 = 2 * c, h1 = 2 * c + 1;
        qsm[r * HDIM + h0] = accq[h0] + sbq[h0];
        qsm[r * HDIM + h1] = accq[h1] + sbq[h1];
        ksm[r * HDIM + h0] = acck[h0] + sbk[h0];
        ksm[r * HDIM + h1] = acck[h1] + sbk[h1];
    }
    __syncthreads();

    // ---- phase 2: logits row r, columns [c*16, c*16+16), softmax, off-diag store ----
    float qv[HDIM];
    {
        float4 q0 = *reinterpret_cast<const float4*>(&qsm[r * HDIM]);
        float4 q1 = *reinterpret_cast<const float4*>(&qsm[r * HDIM + 4]);
        qv[0] = q0.x; qv[1] = q0.y; qv[2] = q0.z; qv[3] = q0.w;
        qv[4] = q1.x; qv[5] = q1.y; qv[6] = q1.z; qv[7] = q1.w;
    }

    float att[16];
    #pragma unroll
    for (int i = 0; i < 16; i++) att[i] = 0.f;

    // att[r][a] = sum_h q[r][h] * kflat[h*64 + a]   (the "reshape, not transpose" semantics)
    #pragma unroll
    for (int h = 0; h < HDIM; h++) {
        const float qh = qv[h];
        #pragma unroll
        for (int j = 0; j < 4; j++) {
            float4 kk = *reinterpret_cast<const float4*>(&ksm[h * ADIM + c * 16 + j * 4]);
            att[4 * j + 0] += qh * kk.x;
            att[4 * j + 1] += qh * kk.y;
            att[4 * j + 2] += qh * kk.z;
            att[4 * j + 3] += qh * kk.w;
        }
    }

    // softmax over 64 columns (16 local + 4-lane shfl reduce)
    float m = att[0];
    #pragma unroll
    for (int i = 1; i < 16; i++) m = fmaxf(m, att[i]);
    m = fmaxf(m, __shfl_xor_sync(0xffffffffu, m, 1));
    m = fmaxf(m, __shfl_xor_sync(0xffffffffu, m, 2));

    float ssum = 0.f;
    #pragma unroll
    for (int i = 0; i < 16; i++) { att[i] = __expf(att[i] - m); ssum += att[i]; }
    ssum += __shfl_xor_sync(0xffffffffu, ssum, 1);
    ssum += __shfl_xor_sync(0xffffffffu, ssum, 2);
    const float inv = __frcp_rn(ssum);

    // off-diagonal gather store: column a -> out col a (a<r) / a-1 (a>r), skip a==r
    float* orow = out + (tb * ADIM + r) * (long long)(ADIM - 1);
    #pragma unroll
    for (int i = 0; i < 16; i++) {
        const int a = c * 16 + i;
        if (a != r) orow[a - (a > r ? 1 : 0)] = att[i] * inv;
    }
}

extern "C" void kernel_launch(void* const* d_in, const int* in_sizes, int n_in,
                              void* d_out, int out_size)
{
    const float* agent = (const float*)d_in[0];
    const float* Wq    = (const float*)d_in[1];
    const float* bq    = (const float*)d_in[2];
    const float* Wk    = (const float*)d_in[3];
    const float* bk    = (const float*)d_in[4];
    float* out = (float*)d_out;

    const int T = 512, B = 32;
    attn_fused_kernel<<<T * B, TPB>>>(agent, Wq, bq, Wk, bk, out);
}

// round 6
// speedup vs baseline: 1.3940x; 1.3940x over previous
#include <cuda_runtime.h>

// Problem constants (T=512, B=32, A=64, N=128, H=8)
#define TPB   256
#define ADIM  64
#define NDIM  128
#define HDIM  8
#define TILES 4     // (t,b) pairs per block -> amortize weight LDS 4x

__global__ __launch_bounds__(TPB, 2)
void attn_fused_kernel(const float* __restrict__ agent,
                       const float* __restrict__ Wq, const float* __restrict__ bq,
                       const float* __restrict__ Wk, const float* __restrict__ bk,
                       float* __restrict__ out)
{
    __shared__ float sWq[HDIM][NDIM];       // transposed: sWq[h][n]
    __shared__ float sWk[HDIM][NDIM];
    __shared__ float sb[2][HDIM];           // [0]=bq, [1]=bk
    __shared__ float qsm[TILES][ADIM * HDIM];   // q[a][h] at a*8+h
    __shared__ float ksm[TILES][ADIM * HDIM];   // k flat row-major; att reads ksm[h*64+a]

    const int tid = threadIdx.x;
    const long long tb0 = (long long)blockIdx.x * TILES;

    // ---- weights (transposed) + biases into smem ----
    for (int i = tid; i < NDIM * HDIM; i += TPB) {
        int n = i >> 3, h = i & 7;
        sWq[h][n] = Wq[i];
        sWk[h][n] = Wk[i];
    }
    if (tid < HDIM) { sb[0][tid] = bq[tid]; sb[1][tid] = bk[tid]; }
    __syncthreads();

    // =========== phase 1: fused Q/K projection for 4 tiles ===========
    {
        const int r = tid >> 2;   // agent row 0..63
        const int c = tid & 3;    // chunk within row

        const float4* srow[TILES];
        #pragma unroll
        for (int t = 0; t < TILES; t++)
            srow[t] = reinterpret_cast<const float4*>(
                agent + (tb0 + t) * (long long)(ADIM * NDIM) + (long long)r * NDIM);

        float accq[TILES][HDIM], acck[TILES][HDIM];
        #pragma unroll
        for (int t = 0; t < TILES; t++)
            #pragma unroll
            for (int h = 0; h < HDIM; h++) { accq[t][h] = 0.f; acck[t][h] = 0.f; }

        #pragma unroll
        for (int k = 0; k < 8; k++) {
            float4 s[TILES];
            #pragma unroll
            for (int t = 0; t < TILES; t++) s[t] = srow[t][c + 4 * k];

            const int nb = (c + 4 * k) * 4;
            #pragma unroll
            for (int h = 0; h < HDIM; h++) {
                const float4 wq = *reinterpret_cast<const float4*>(&sWq[h][nb]);
                const float4 wk = *reinterpret_cast<const float4*>(&sWk[h][nb]);
                #pragma unroll
                for (int t = 0; t < TILES; t++) {
                    accq[t][h] += s[t].x * wq.x + s[t].y * wq.y + s[t].z * wq.z + s[t].w * wq.w;
                    acck[t][h] += s[t].x * wk.x + s[t].y * wk.y + s[t].z * wk.z + s[t].w * wk.w;
                }
            }
        }

        // Halving butterfly reduce across the 4 lanes of this row.
        // Stage 1 (xor 1): even lane keeps q-sums, odd lane keeps k-sums.
        // Stage 2 (xor 2): bit1=0 keeps h0..3, bit1=1 keeps h4..7.
        const int matk = c & 1;               // 0 -> this lane owns q, 1 -> k
        const int hbase = (c & 2) ? 4 : 0;    // h-half this lane owns
        #pragma unroll
        for (int t = 0; t < TILES; t++) {
            float v[HDIM];
            #pragma unroll
            for (int h = 0; h < HDIM; h++) {
                // send what the partner keeps, receive what we keep
                float sent = matk ? accq[t][h] : acck[t][h];
                float recv = __shfl_xor_sync(0xffffffffu, sent, 1);
                v[h] = (matk ? acck[t][h] : accq[t][h]) + recv;
            }
            float f[4];
            #pragma unroll
            for (int i = 0; i < 4; i++) {
                float sent = (c & 2) ? v[i] : v[i + 4];
                float recv = __shfl_xor_sync(0xffffffffu, sent, 2);
                f[i] = ((c & 2) ? v[i + 4] : v[i]) + recv;
            }
            float* dst = matk ? ksm[t] : qsm[t];
            #pragma unroll
            for (int i = 0; i < 4; i++)
                dst[r * HDIM + hbase + i] = f[i] + sb[matk][hbase + i];
        }
    }
    __syncthreads();

    // =========== phase 2: logits + softmax + off-diag store ===========
    // thread = (row-pair, 8-column chunk): halves k-tile LDS per row vs 1x16
    {
        const int rp = tid >> 3;        // 0..31
        const int cc = tid & 7;         // column chunk 0..7
        const int r0 = rp * 2, r1 = r0 + 1;

        #pragma unroll
        for (int t = 0; t < TILES; t++) {
            float q0[HDIM], q1[HDIM];
            {
                float4 a = *reinterpret_cast<const float4*>(&qsm[t][r0 * HDIM]);
                float4 b = *reinterpret_cast<const float4*>(&qsm[t][r0 * HDIM + 4]);
                q0[0]=a.x; q0[1]=a.y; q0[2]=a.z; q0[3]=a.w;
                q0[4]=b.x; q0[5]=b.y; q0[6]=b.z; q0[7]=b.w;
                float4 e = *reinterpret_cast<const float4*>(&qsm[t][r1 * HDIM]);
                float4 d = *reinterpret_cast<const float4*>(&qsm[t][r1 * HDIM + 4]);
                q1[0]=e.x; q1[1]=e.y; q1[2]=e.z; q1[3]=e.w;
                q1[4]=d.x; q1[5]=d.y; q1[6]=d.z; q1[7]=d.w;
            }

            float a0[8], a1[8];
            #pragma unroll
            for (int i = 0; i < 8; i++) { a0[i] = 0.f; a1[i] = 0.f; }

            // att[r][a] = sum_h q[r][h] * kflat[h*64 + a]  (reshape semantics)
            #pragma unroll
            for (int h = 0; h < HDIM; h++) {
                const float4 ka = *reinterpret_cast<const float4*>(&ksm[t][h * ADIM + cc * 8]);
                const float4 kb = *reinterpret_cast<const float4*>(&ksm[t][h * ADIM + cc * 8 + 4]);
                const float x0 = q0[h], x1 = q1[h];
                a0[0] += x0 * ka.x; a0[1] += x0 * ka.y; a0[2] += x0 * ka.z; a0[3] += x0 * ka.w;
                a0[4] += x0 * kb.x; a0[5] += x0 * kb.y; a0[6] += x0 * kb.z; a0[7] += x0 * kb.w;
                a1[0] += x1 * ka.x; a1[1] += x1 * ka.y; a1[2] += x1 * ka.z; a1[3] += x1 * ka.w;
                a1[4] += x1 * kb.x; a1[5] += x1 * kb.y; a1[6] += x1 * kb.z; a1[7] += x1 * kb.w;
            }

            // softmax over 64 cols: 8 local + reduce over the 8 lanes of this row-pair
            float m0 = a0[0], m1 = a1[0];
            #pragma unroll
            for (int i = 1; i < 8; i++) { m0 = fmaxf(m0, a0[i]); m1 = fmaxf(m1, a1[i]); }
            #pragma unroll
            for (int s = 1; s < 8; s <<= 1) {
                m0 = fmaxf(m0, __shfl_xor_sync(0xffffffffu, m0, s));
                m1 = fmaxf(m1, __shfl_xor_sync(0xffffffffu, m1, s));
            }
            float s0 = 0.f, s1 = 0.f;
            #pragma unroll
            for (int i = 0; i < 8; i++) {
                a0[i] = __expf(a0[i] - m0); s0 += a0[i];
                a1[i] = __expf(a1[i] - m1); s1 += a1[i];
            }
            #pragma unroll
            for (int s = 1; s < 8; s <<= 1) {
                s0 += __shfl_xor_sync(0xffffffffu, s0, s);
                s1 += __shfl_xor_sync(0xffffffffu, s1, s);
            }
            const float inv0 = __frcp_rn(s0);
            const float inv1 = __frcp_rn(s1);

            // off-diagonal gather store: col a -> a (a<r) / a-1 (a>r), skip a==r
            const long long tb = tb0 + t;
            float* o0 = out + (tb * ADIM + r0) * (long long)(ADIM - 1);
            float* o1 = out + (tb * ADIM + r1) * (long long)(ADIM - 1);
            #pragma unroll
            for (int i = 0; i < 8; i++) {
                const int a = cc * 8 + i;
                if (a != r0) o0[a - (a > r0 ? 1 : 0)] = a0[i] * inv0;
                if (a != r1) o1[a - (a > r1 ? 1 : 0)] = a1[i] * inv1;
            }
        }
    }
}

extern "C" void kernel_launch(void* const* d_in, const int* in_sizes, int n_in,
                              void* d_out, int out_size)
{
    const float* agent = (const float*)d_in[0];
    const float* Wq    = (const float*)d_in[1];
    const float* bq    = (const float*)d_in[2];
    const float* Wk    = (const float*)d_in[3];
    const float* bk    = (const float*)d_in[4];
    float* out = (float*)d_out;

    const int T = 512, B = 32;
    attn_fused_kernel<<<(T * B) / TILES, TPB>>>(agent, Wq, bq, Wk, bk, out);
}